// round 15
// baseline (speedup 1.0000x reference)
#include <cuda_runtime.h>
#include <cuda_bf16.h>

// GraphConvDistanceLayer: out[i] = sum_{e: rows[e]==i} Param_W[params[e]] * x[cols[e]]
//                                 + Param_b[b_params[i]]
//
// Inputs (metadata order):
//   d_in[0] = x        float32 [N]      N = 262144
//   d_in[1] = Param_W  float32 [1280]
//   d_in[2] = Param_b  float32 [16]
//   d_in[3] = w_rows   int32   [E]      E = 16777216
//   d_in[4] = w_cols   int32   [E]
//   d_in[5] = w_params int32   [E]
//   d_in[6] = b_params int32   [N]
// Output: float32 [N]
//
// CLOSED MODEL (R5-R14): LSU/L1tex op-rate floor. Per SM: E/148 gather
// sectors (~1 cyc/wavefront) + E/148 REDG lanes (~1.29 cyc, spread) share
// one pipe -> ~259K cyc predicted vs ~250K observed. fp16/__ldcs/carveout/
// MLP all proven neutral, as the model requires. Total = kernel (132us) +
// ~3.5us fixed graph-replay overhead (2 nodes). R15: last knob - 512-thr
// blocks, bias items first (uniform final wave).

#define GCD_NPARAMS 1280

// ---------------------------------------------------------------------------
// Fused kernel: item space = [0, n4) bias-quads, [n4, n4+e4) edge-quads,
// [n4+e4, n4+e4+ntail) scalar bias tail. out pre-zeroed by memset node.
// ---------------------------------------------------------------------------
__global__ __launch_bounds__(512)
void gcd_fused(const float* __restrict__ x,
               const float* __restrict__ Pw,
               const float* __restrict__ Pb,
               const int4* __restrict__ rows,
               const int4* __restrict__ cols,
               const int4* __restrict__ params,
               const int* __restrict__ bp,
               float* __restrict__ out,
               int e4, int n4, int ntail, int N) {
    __shared__ float sPw[GCD_NPARAMS];
    for (int i = threadIdx.x; i < GCD_NPARAMS; i += blockDim.x)
        sPw[i] = Pw[i];
    __syncthreads();

    int i = blockIdx.x * blockDim.x + threadIdx.x;

    if (i < n4) {
        // ---- bias quad (cheap items first; final wave is uniform edges) ----
        int4 b = __ldcs(&((const int4*)bp)[i]);
        int o = i * 4;
        atomicAdd(&out[o + 0], __ldg(&Pb[b.x]));
        atomicAdd(&out[o + 1], __ldg(&Pb[b.y]));
        atomicAdd(&out[o + 2], __ldg(&Pb[b.z]));
        atomicAdd(&out[o + 3], __ldg(&Pb[b.w]));
    } else if (i < n4 + e4) {
        // ---- edge quad ----
        int j = i - n4;
        int4 c = __ldcs(&cols[j]);
        int4 p = __ldcs(&params[j]);
        int4 r = __ldcs(&rows[j]);

        // 4 independent x-gathers (latency overlapped).
        float xa = __ldg(&x[c.x]);
        float xb = __ldg(&x[c.y]);
        float xc = __ldg(&x[c.z]);
        float xd = __ldg(&x[c.w]);

        float v0 = sPw[p.x] * xa;
        float v1 = sPw[p.y] * xb;
        float v2 = sPw[p.z] * xc;
        float v3 = sPw[p.w] * xd;

        atomicAdd(&out[r.x], v0);
        atomicAdd(&out[r.y], v1);
        atomicAdd(&out[r.z], v2);
        atomicAdd(&out[r.w], v3);
    } else if (i < n4 + e4 + ntail) {
        // ---- scalar bias tail (N % 4; zero for N = 262144) ----
        int o = n4 * 4 + (i - n4 - e4);
        if (o < N)
            atomicAdd(&out[o], __ldg(&Pb[__ldg(&bp[o])]));
    }
}

// Scalar edge tail (E % 4 != 0) — defensive; E = 2^24 so normally unused.
// out is zero-initialized and all writes atomic, so ordering is free.
__global__ __launch_bounds__(128)
void gcd_edge_tail(const float* __restrict__ x,
                   const float* __restrict__ Pw,
                   const int* __restrict__ rows,
                   const int* __restrict__ cols,
                   const int* __restrict__ params,
                   float* __restrict__ out,
                   int start, int E) {
    int e = start + blockIdx.x * blockDim.x + threadIdx.x;
    if (e < E) {
        float v = __ldg(&Pw[__ldg(&params[e])]) * __ldg(&x[__ldg(&cols[e])]);
        atomicAdd(&out[__ldg(&rows[e])], v);
    }
}

extern "C" void kernel_launch(void* const* d_in, const int* in_sizes, int n_in,
                              void* d_out, int out_size) {
    const float* x   = (const float*)d_in[0];
    const float* Pw  = (const float*)d_in[1];
    const float* Pb  = (const float*)d_in[2];
    const int* rows  = (const int*)d_in[3];
    const int* cols  = (const int*)d_in[4];
    const int* prm   = (const int*)d_in[5];
    const int* bp    = (const int*)d_in[6];
    float* out       = (float*)d_out;

    const int N = out_size;
    const int E = in_sizes[3];

    // 0) zero out (clears the 0xAA poison; capture-legal memset node)
    cudaMemsetAsync(out, 0, (size_t)N * sizeof(float), 0);

    // 1) fused bias + edges, all-atomic accumulation, 512-thread blocks
    const int e4 = E >> 2;
    const int n4 = N >> 2;
    const int ntail = N - (n4 << 2);
    const int total = n4 + e4 + ntail;
    if (total > 0) {
        gcd_fused<<<(total + 511) / 512, 512>>>(
            x, Pw, Pb,
            (const int4*)rows, (const int4*)cols, (const int4*)prm,
            bp, out, e4, n4, ntail, N);
    }

    // 2) defensive scalar edge tail (E % 4 != 0; unused for E = 2^24)
    const int tail_start = e4 << 2;
    const int tail = E - tail_start;
    if (tail > 0) {
        gcd_edge_tail<<<(tail + 127) / 128, 128>>>(
            x, Pw, rows, cols, prm, out, tail_start, E);
    }
}

// round 16
// speedup vs baseline: 1.0129x; 1.0129x over previous
#include <cuda_runtime.h>
#include <cuda_bf16.h>

// GraphConvDistanceLayer: out[i] = sum_{e: rows[e]==i} Param_W[params[e]] * x[cols[e]]
//                                 + Param_b[b_params[i]]
//
// Inputs (metadata order):
//   d_in[0] = x        float32 [N]      N = 262144
//   d_in[1] = Param_W  float32 [1280]
//   d_in[2] = Param_b  float32 [16]
//   d_in[3] = w_rows   int32   [E]      E = 16777216
//   d_in[4] = w_cols   int32   [E]
//   d_in[5] = w_params int32   [E]
//   d_in[6] = b_params int32   [N]
// Output: float32 [N]
//
// FINAL CONFIG (= R14 champion). Closed model (R5-R15): LSU/L1tex op-rate
// floor — per SM, E/148 divergent gather wavefronts (~1 cyc) + E/148 spread
// REDG lanes (~1.29 cyc) share one pipe => ~259K cyc predicted, ~250K
// observed (saturated). Probed to neutral/negative: edges/thread {4 ok,
// 8 worse}, block {256 ok, 512 worse}, fp16-x worse, __ldcs neutral,
// carveout neutral. Structure: memset node + ONE fused all-atomic kernel
// (edge-quads then bias-quads); ~3.5us is fixed graph-replay overhead.

#define GCD_NPARAMS 1280

// ---------------------------------------------------------------------------
// Fused kernel: item space = [0, e4) edge-quads, [e4, e4+n4) bias-quads,
// [e4+n4, e4+n4+ntail) scalar bias tail. out pre-zeroed by memset node.
//  - edge-quad: 3x coalesced LDG.128 index loads (__ldcs, evict-first),
//    4 divergent x-gathers, Param_W from smem, 4 REDG atomics
//  - bias-quad: 1x LDG.128 of b_params, Pb via __ldg (16 floats, L1-resident),
//    4 REDG atomics
// ---------------------------------------------------------------------------
__global__ __launch_bounds__(256)
void gcd_fused(const float* __restrict__ x,
               const float* __restrict__ Pw,
               const float* __restrict__ Pb,
               const int4* __restrict__ rows,
               const int4* __restrict__ cols,
               const int4* __restrict__ params,
               const int* __restrict__ bp,
               float* __restrict__ out,
               int e4, int n4, int ntail, int N) {
    __shared__ float sPw[GCD_NPARAMS];
    for (int i = threadIdx.x; i < GCD_NPARAMS; i += blockDim.x)
        sPw[i] = Pw[i];
    __syncthreads();

    int i = blockIdx.x * blockDim.x + threadIdx.x;

    if (i < e4) {
        // ---- edge quad ----
        int4 c = __ldcs(&cols[i]);
        int4 p = __ldcs(&params[i]);
        int4 r = __ldcs(&rows[i]);

        // 4 independent x-gathers (latency overlapped).
        float xa = __ldg(&x[c.x]);
        float xb = __ldg(&x[c.y]);
        float xc = __ldg(&x[c.z]);
        float xd = __ldg(&x[c.w]);

        float v0 = sPw[p.x] * xa;
        float v1 = sPw[p.y] * xb;
        float v2 = sPw[p.z] * xc;
        float v3 = sPw[p.w] * xd;

        atomicAdd(&out[r.x], v0);
        atomicAdd(&out[r.y], v1);
        atomicAdd(&out[r.z], v2);
        atomicAdd(&out[r.w], v3);
    } else if (i < e4 + n4) {
        // ---- bias quad ----
        int j = i - e4;                       // quad index into b_params
        int4 b = __ldcs(&((const int4*)bp)[j]);
        int o = j * 4;
        atomicAdd(&out[o + 0], __ldg(&Pb[b.x]));
        atomicAdd(&out[o + 1], __ldg(&Pb[b.y]));
        atomicAdd(&out[o + 2], __ldg(&Pb[b.z]));
        atomicAdd(&out[o + 3], __ldg(&Pb[b.w]));
    } else if (i < e4 + n4 + ntail) {
        // ---- scalar bias tail (N % 4; zero for N = 262144) ----
        int o = n4 * 4 + (i - e4 - n4);
        if (o < N)
            atomicAdd(&out[o], __ldg(&Pb[__ldg(&bp[o])]));
    }
}

// Scalar edge tail (E % 4 != 0) — defensive; E = 2^24 so normally unused.
// out is zero-initialized and all writes atomic, so ordering is free.
__global__ __launch_bounds__(128)
void gcd_edge_tail(const float* __restrict__ x,
                   const float* __restrict__ Pw,
                   const int* __restrict__ rows,
                   const int* __restrict__ cols,
                   const int* __restrict__ params,
                   float* __restrict__ out,
                   int start, int E) {
    int e = start + blockIdx.x * blockDim.x + threadIdx.x;
    if (e < E) {
        float v = __ldg(&Pw[__ldg(&params[e])]) * __ldg(&x[__ldg(&cols[e])]);
        atomicAdd(&out[__ldg(&rows[e])], v);
    }
}

extern "C" void kernel_launch(void* const* d_in, const int* in_sizes, int n_in,
                              void* d_out, int out_size) {
    const float* x   = (const float*)d_in[0];
    const float* Pw  = (const float*)d_in[1];
    const float* Pb  = (const float*)d_in[2];
    const int* rows  = (const int*)d_in[3];
    const int* cols  = (const int*)d_in[4];
    const int* prm   = (const int*)d_in[5];
    const int* bp    = (const int*)d_in[6];
    float* out       = (float*)d_out;

    const int N = out_size;
    const int E = in_sizes[3];

    // 0) zero out (clears the 0xAA poison; capture-legal memset node)
    cudaMemsetAsync(out, 0, (size_t)N * sizeof(float), 0);

    // 1) fused edges + bias, all-atomic accumulation, 256-thread blocks
    const int e4 = E >> 2;
    const int n4 = N >> 2;
    const int ntail = N - (n4 << 2);
    const int total = e4 + n4 + ntail;
    if (total > 0) {
        gcd_fused<<<(total + 255) / 256, 256>>>(
            x, Pw, Pb,
            (const int4*)rows, (const int4*)cols, (const int4*)prm,
            bp, out, e4, n4, ntail, N);
    }

    // 2) defensive scalar edge tail (E % 4 != 0; unused for E = 2^24)
    const int tail_start = e4 << 2;
    const int tail = E - tail_start;
    if (tail > 0) {
        gcd_edge_tail<<<(tail + 127) / 128, 128>>>(
            x, Pw, rows, cols, prm, out, tail_start, E);
    }
}